// round 1
// baseline (speedup 1.0000x reference)
#include <cuda_runtime.h>
#include <cuda_bf16.h>
#include <math.h>

// Problem constants (fixed shapes from setup_inputs)
#define BATCH 16
#define INCH  256
#define HH    48
#define WW    48
#define HWPX  (HH*WW)        // 2304
#define SEQ   2048
#define CTXD  128
#define EMB   256

// -------------------- device scratch (allocation-free) --------------------
__device__ __align__(16) float g_Weff[EMB * INCH];
__device__ __align__(16) float g_beff[EMB];
__device__ __align__(16) float g_Q[BATCH * HWPX * EMB];   // 37.7 MB
__device__ __align__(16) float g_K[BATCH * SEQ * EMB];    // 33.5 MB
__device__ __align__(16) float g_V[BATCH * SEQ * EMB];    // 33.5 MB
__device__ __align__(16) float g_O[BATCH * HWPX * EMB];   // 37.7 MB
__device__ int g_mask_mode;   // 0 = byte(bool), 1 = int32, 2 = float32

// -------------------- mask dtype detection --------------------
// Scan first `nbytes` raw bytes of the mask buffer (safe for every candidate
// dtype since element count >= nbytes). Classify by which byte positions
// (mod 4) are nonzero:
//   bool/int8 : nonzero bytes appear at positions == 1 (mod 4)
//   int32 (1) : nonzero only at positions == 0 (mod 4)   (little-endian)
//   float(1.0): nonzero only at positions 2,3 (mod 4)  (0x3F800000)
__global__ void detect_mask_kernel(const unsigned char* __restrict__ m, int nbytes) {
    __shared__ int c1, c23;
    if (threadIdx.x == 0) { c1 = 0; c23 = 0; }
    __syncthreads();
    int l1 = 0, l23 = 0;
    for (int i = threadIdx.x; i < nbytes; i += blockDim.x) {
        unsigned char v = m[i];
        if (v) {
            int r = i & 3;
            if (r == 1) l1++;
            else if (r >= 2) l23++;
        }
    }
    if (l1) atomicAdd(&c1, l1);
    if (l23) atomicAdd(&c23, l23);
    __syncthreads();
    if (threadIdx.x == 0)
        g_mask_mode = (c1 > 0) ? 0 : ((c23 > 0) ? 2 : 1);
}

// -------------------- Weff = Wq @ W_in,  beff = Wq @ b_in + bq --------------------
__global__ void weff_kernel(const float* __restrict__ Wq,
                            const float* __restrict__ W_in,
                            const float* __restrict__ b_in,
                            const float* __restrict__ bq) {
    __shared__ float wqs[EMB];
    int e = blockIdx.x;
    int c = threadIdx.x;
    wqs[c] = Wq[e * EMB + c];
    __syncthreads();
    float s = 0.f;
    #pragma unroll 8
    for (int f = 0; f < EMB; f++)
        s += wqs[f] * W_in[f * INCH + c];
    g_Weff[e * INCH + c] = s;
    if (c == 0) {
        float sb = 0.f;
        for (int f = 0; f < EMB; f++) sb += wqs[f] * b_in[f];
        g_beff[e] = sb + bq[e];
    }
}

// -------------------- generic strided fp32 GEMM --------------------
// C[m,n] = alpha * sum_k A[m,k]*B[n,k]  (+ bias)  (mask -> -1e9)
// A[m,k] at A + bz*a_bs + m*lda_m + k*lda_k
// B[n,k] at B + bz*b_bs + n*ldb_n + k*ldb_k
// C[m,n] at C + bz*c_bs + m*ldc_m + n*ldc_n
// Tiles: 128x128x16, 256 threads, 8x8 per thread. All dims must divide tiles.
__global__ void __launch_bounds__(256)
gemm_kernel(const float* __restrict__ A, long long a_bs, int lda_m, int lda_k,
            const float* __restrict__ B, long long b_bs, int ldb_n, int ldb_k,
            float*       __restrict__ C, long long c_bs, int ldc_m, int ldc_n,
            const float* __restrict__ bias, int bias_per_m, float alpha,
            const void*  __restrict__ mask, long long mask_bs,
            int M, int N, int K)
{
    __shared__ float As[16][132];
    __shared__ float Bs[16][132];

    const int bz = blockIdx.z;
    const float* Ab = A + (long long)bz * a_bs;
    const float* Bb = B + (long long)bz * b_bs;
    float*       Cb = C + (long long)bz * c_bs;
    const int m0 = blockIdx.y * 128;
    const int n0 = blockIdx.x * 128;
    const int tid = threadIdx.x;
    const int tx = tid & 15;
    const int ty = tid >> 4;

    float acc[8][8];
    #pragma unroll
    for (int i = 0; i < 8; i++)
        #pragma unroll
        for (int j = 0; j < 8; j++) acc[i][j] = 0.f;

    for (int k0 = 0; k0 < K; k0 += 16) {
        // ---- load A tile: As[k][m] ----
        if (lda_k == 1) {
            int k = tid & 15, mb = tid >> 4;
            #pragma unroll
            for (int i = 0; i < 8; i++) {
                int m = mb + i * 16;
                As[k][m] = Ab[(long long)(m0 + m) * lda_m + (k0 + k)];
            }
        } else {
            int m = tid & 127, kb = tid >> 7;
            #pragma unroll
            for (int i = 0; i < 8; i++) {
                int k = kb + i * 2;
                As[k][m] = Ab[(long long)(m0 + m) * lda_m + (long long)(k0 + k) * lda_k];
            }
        }
        // ---- load B tile: Bs[k][n] ----
        if (ldb_k == 1) {
            int k = tid & 15, nb = tid >> 4;
            #pragma unroll
            for (int i = 0; i < 8; i++) {
                int n = nb + i * 16;
                Bs[k][n] = Bb[(long long)(n0 + n) * ldb_n + (k0 + k)];
            }
        } else {
            int n = tid & 127, kb = tid >> 7;
            #pragma unroll
            for (int i = 0; i < 8; i++) {
                int k = kb + i * 2;
                Bs[k][n] = Bb[(long long)(n0 + n) * ldb_n + (long long)(k0 + k) * ldb_k];
            }
        }
        __syncthreads();

        #pragma unroll
        for (int k = 0; k < 16; k++) {
            float4 a0 = *(const float4*)&As[k][ty * 4];
            float4 a1 = *(const float4*)&As[k][64 + ty * 4];
            float4 b0 = *(const float4*)&Bs[k][tx * 4];
            float4 b1 = *(const float4*)&Bs[k][64 + tx * 4];
            float af[8] = {a0.x, a0.y, a0.z, a0.w, a1.x, a1.y, a1.z, a1.w};
            float bf[8] = {b0.x, b0.y, b0.z, b0.w, b1.x, b1.y, b1.z, b1.w};
            #pragma unroll
            for (int i = 0; i < 8; i++)
                #pragma unroll
                for (int j = 0; j < 8; j++)
                    acc[i][j] += af[i] * bf[j];
        }
        __syncthreads();
    }

    // ---- epilogue ----
    const int mmode = mask ? g_mask_mode : 0;
    #pragma unroll
    for (int i = 0; i < 8; i++) {
        int mi = (i < 4) ? (ty * 4 + i) : (64 + ty * 4 + i - 4);
        int m = m0 + mi;
        float bm = (bias && bias_per_m) ? bias[m] : 0.f;
        #pragma unroll
        for (int j = 0; j < 8; j++) {
            int ni = (j < 4) ? (tx * 4 + j) : (64 + tx * 4 + j - 4);
            int n = n0 + ni;
            float v = acc[i][j] * alpha + bm;
            if (bias && !bias_per_m) v += bias[n];
            if (mask) {
                long long idx = (long long)bz * mask_bs + (long long)m * N + n;
                bool mk;
                if (mmode == 0)      mk = ((const unsigned char*)mask)[idx] != 0;
                else if (mmode == 1) mk = ((const int*)mask)[idx] != 0;
                else                 mk = ((const float*)mask)[idx] != 0.f;
                if (mk) v = -1e9f;
            }
            Cb[(long long)m * ldc_m + (long long)n * ldc_n] = v;
        }
    }
}

// -------------------- row softmax over SEQ=2048, in place --------------------
__global__ void __launch_bounds__(256) softmax_kernel(float* __restrict__ att) {
    __shared__ float red[8];
    float* p = att + (long long)blockIdx.x * SEQ;
    const int t = threadIdx.x;
    float4* p4 = (float4*)p;
    float4 a = p4[t];
    float4 b = p4[t + 256];
    float x[8] = {a.x, a.y, a.z, a.w, b.x, b.y, b.z, b.w};

    float m = x[0];
    #pragma unroll
    for (int i = 1; i < 8; i++) m = fmaxf(m, x[i]);
    #pragma unroll
    for (int o = 16; o; o >>= 1) m = fmaxf(m, __shfl_xor_sync(0xffffffffu, m, o));
    if ((t & 31) == 0) red[t >> 5] = m;
    __syncthreads();
    float mm = red[0];
    #pragma unroll
    for (int i = 1; i < 8; i++) mm = fmaxf(mm, red[i]);
    __syncthreads();

    float e[8];
    float s = 0.f;
    #pragma unroll
    for (int i = 0; i < 8; i++) { e[i] = __expf(x[i] - mm); s += e[i]; }
    #pragma unroll
    for (int o = 16; o; o >>= 1) s += __shfl_xor_sync(0xffffffffu, s, o);
    if ((t & 31) == 0) red[t >> 5] = s;
    __syncthreads();
    float ss = red[0];
    #pragma unroll
    for (int i = 1; i < 8; i++) ss += red[i];
    float inv = 1.f / ss;

    a = make_float4(e[0] * inv, e[1] * inv, e[2] * inv, e[3] * inv);
    b = make_float4(e[4] * inv, e[5] * inv, e[6] * inv, e[7] * inv);
    p4[t] = a;
    p4[t + 256] = b;
}

// -------------------- launch --------------------
extern "C" void kernel_launch(void* const* d_in, const int* in_sizes, int n_in,
                              void* d_out, int out_size) {
    const float* x     = (const float*)d_in[0];
    const float* ctx   = (const float*)d_in[1];
    const void*  mask  = d_in[2];
    const float* W_in  = (const float*)d_in[3];
    const float* b_in  = (const float*)d_in[4];
    const float* Wq    = (const float*)d_in[5];
    const float* bq    = (const float*)d_in[6];
    const float* Wk    = (const float*)d_in[7];
    const float* bk    = (const float*)d_in[8];
    const float* Wv    = (const float*)d_in[9];
    const float* bv    = (const float*)d_in[10];
    const float* W_out = (const float*)d_in[11];
    const float* b_out = (const float*)d_in[12];

    float* out = (float*)d_out;                              // [16,256,48,48]
    float* att = out + (long long)BATCH * INCH * HWPX;       // [16,2304,2048]

    float *pQ, *pK, *pV, *pO, *pW, *pb;
    cudaGetSymbolAddress((void**)&pQ, g_Q);
    cudaGetSymbolAddress((void**)&pK, g_K);
    cudaGetSymbolAddress((void**)&pV, g_V);
    cudaGetSymbolAddress((void**)&pO, g_O);
    cudaGetSymbolAddress((void**)&pW, g_Weff);
    cudaGetSymbolAddress((void**)&pb, g_beff);

    int scan = 65536;
    if (in_sizes[2] < scan) scan = in_sizes[2];
    detect_mask_kernel<<<1, 256>>>((const unsigned char*)mask, scan);

    weff_kernel<<<EMB, 256>>>(Wq, W_in, b_in, bq);

    // Q[b,p,e] = sum_c x[b,c,p] * Weff[e,c] + beff[e]
    gemm_kernel<<<dim3(EMB / 128, HWPX / 128, BATCH), 256>>>(
        x, (long long)INCH * HWPX, 1, HWPX,
        pW, 0, INCH, 1,
        pQ, (long long)HWPX * EMB, EMB, 1,
        pb, 0, 1.f, nullptr, 0,
        HWPX, EMB, INCH);

    // K[b,s,e] = sum_d ctx[b,s,d] * Wk[e,d] + bk[e]
    gemm_kernel<<<dim3(EMB / 128, SEQ / 128, BATCH), 256>>>(
        ctx, (long long)SEQ * CTXD, CTXD, 1,
        Wk, 0, CTXD, 1,
        pK, (long long)SEQ * EMB, EMB, 1,
        bk, 0, 1.f, nullptr, 0,
        SEQ, EMB, CTXD);

    // V[b,s,e]
    gemm_kernel<<<dim3(EMB / 128, SEQ / 128, BATCH), 256>>>(
        ctx, (long long)SEQ * CTXD, CTXD, 1,
        Wv, 0, CTXD, 1,
        pV, (long long)SEQ * EMB, EMB, 1,
        bv, 0, 1.f, nullptr, 0,
        SEQ, EMB, CTXD);

    // logits[b,p,s] = (1/16) * sum_e Q[b,p,e]*K[b,s,e]; masked -> -1e9; into att output
    gemm_kernel<<<dim3(SEQ / 128, HWPX / 128, BATCH), 256>>>(
        pQ, (long long)HWPX * EMB, EMB, 1,
        pK, (long long)SEQ * EMB, EMB, 1,
        att, (long long)HWPX * SEQ, SEQ, 1,
        nullptr, 0, 0.0625f,
        mask, (long long)HWPX * SEQ,
        HWPX, SEQ, EMB);

    // softmax rows (in place in att output)
    softmax_kernel<<<BATCH * HWPX, 256>>>(att);

    // O[b,p,e] = sum_s att[b,p,s] * V[b,s,e]
    gemm_kernel<<<dim3(EMB / 128, HWPX / 128, BATCH), 256>>>(
        att, (long long)HWPX * SEQ, SEQ, 1,
        pV, (long long)SEQ * EMB, 1, EMB,
        pO, (long long)HWPX * EMB, EMB, 1,
        nullptr, 0, 1.f, nullptr, 0,
        HWPX, EMB, SEQ);

    // out[b,c,p] = sum_e W_out[c,e] * O[b,p,e] + b_out[c]
    gemm_kernel<<<dim3(HWPX / 128, INCH / 128, BATCH), 256>>>(
        W_out, 0, EMB, 1,
        pO, (long long)HWPX * EMB, EMB, 1,
        out, (long long)INCH * HWPX, HWPX, 1,
        b_out, 1, 1.f, nullptr, 0,
        INCH, HWPX, EMB);
}

// round 7
// speedup vs baseline: 2.9575x; 2.9575x over previous
#include <cuda_runtime.h>
#include <cuda_bf16.h>
#include <cstdint>

// Problem constants
#define BATCH 16
#define INCH  256
#define HWPX  2304
#define SEQ   2048
#define CTXD  128
#define EMB   256

// ======================= PTX helpers =======================
__device__ __forceinline__ uint32_t smem_u32(const void* p) {
    uint32_t a;
    asm("{ .reg .u64 t; cvta.to.shared.u64 t, %1; cvt.u32.u64 %0, t; }" : "=r"(a) : "l"(p));
    return a;
}
__device__ __forceinline__ void cp_async16(uint32_t dst, const void* src) {
    asm volatile("cp.async.cg.shared.global [%0], [%1], 16;" :: "r"(dst), "l"(src));
}
#define CP_COMMIT() asm volatile("cp.async.commit_group;" ::: "memory")
#define CP_WAIT0()  asm volatile("cp.async.wait_group 0;" ::: "memory")
#define CP_WAIT1()  asm volatile("cp.async.wait_group 1;" ::: "memory")

__device__ __forceinline__ void ldsm4(uint32_t* r, uint32_t addr) {
    asm volatile("ldmatrix.sync.aligned.m8n8.x4.shared.b16 {%0,%1,%2,%3}, [%4];"
        : "=r"(r[0]), "=r"(r[1]), "=r"(r[2]), "=r"(r[3]) : "r"(addr));
}
__device__ __forceinline__ void mma16816(float* c, const uint32_t* a, uint32_t b0, uint32_t b1) {
    asm volatile("mma.sync.aligned.m16n8k16.row.col.f32.bf16.bf16.f32 "
        "{%0,%1,%2,%3}, {%4,%5,%6,%7}, {%8,%9}, {%0,%1,%2,%3};"
        : "+f"(c[0]), "+f"(c[1]), "+f"(c[2]), "+f"(c[3])
        : "r"(a[0]), "r"(a[1]), "r"(a[2]), "r"(a[3]), "r"(b0), "r"(b1));
}

// ======================= scratch =======================
__device__ __align__(16) float g_Weff[EMB * INCH];
__device__ __align__(16) float g_beff[EMB];
__device__ __align__(16) __nv_bfloat16 g_xTb[BATCH * HWPX * INCH];
__device__ __align__(16) __nv_bfloat16 g_Weffb[EMB * INCH];
__device__ __align__(16) __nv_bfloat16 g_Wkb[EMB * CTXD];
__device__ __align__(16) __nv_bfloat16 g_Wvh[EMB * CTXD];
__device__ __align__(16) __nv_bfloat16 g_Wvl[EMB * CTXD];
__device__ __align__(16) __nv_bfloat16 g_Wouth[INCH * EMB];
__device__ __align__(16) __nv_bfloat16 g_Woutl[INCH * EMB];
__device__ __align__(16) __nv_bfloat16 g_ctxh[BATCH * SEQ * CTXD];
__device__ __align__(16) __nv_bfloat16 g_ctxl[BATCH * SEQ * CTXD];
__device__ __align__(16) __nv_bfloat16 g_Qb[BATCH * HWPX * EMB];
__device__ __align__(16) __nv_bfloat16 g_Kb[BATCH * SEQ * EMB];
__device__ __align__(16) __nv_bfloat16 g_Vth[BATCH * EMB * SEQ];
__device__ __align__(16) __nv_bfloat16 g_Vtl[BATCH * EMB * SEQ];
__device__ __align__(16) __nv_bfloat16 g_atth[(size_t)BATCH * HWPX * SEQ];
__device__ __align__(16) __nv_bfloat16 g_attl[(size_t)BATCH * HWPX * SEQ];
__device__ __align__(16) __nv_bfloat16 g_Oh[BATCH * HWPX * EMB];
__device__ __align__(16) __nv_bfloat16 g_Ol[BATCH * HWPX * EMB];
__device__ int g_mask_mode;

// ======================= mask dtype detection =======================
__global__ void detect_mask_kernel(const unsigned char* __restrict__ m, int nbytes) {
    __shared__ int c1, c23;
    if (threadIdx.x == 0) { c1 = 0; c23 = 0; }
    __syncthreads();
    int l1 = 0, l23 = 0;
    for (int i = threadIdx.x; i < nbytes; i += blockDim.x) {
        unsigned char v = m[i];
        if (v) { int r = i & 3; if (r == 1) l1++; else if (r >= 2) l23++; }
    }
    if (l1) atomicAdd(&c1, l1);
    if (l23) atomicAdd(&c23, l23);
    __syncthreads();
    if (threadIdx.x == 0) g_mask_mode = (c1 > 0) ? 0 : ((c23 > 0) ? 2 : 1);
}

// ======================= Weff = Wq @ W_in (fp32) =======================
__global__ void weff_kernel(const float* __restrict__ Wq, const float* __restrict__ W_in,
                            const float* __restrict__ b_in, const float* __restrict__ bq) {
    __shared__ float wqs[EMB];
    int e = blockIdx.x, c = threadIdx.x;
    wqs[c] = Wq[e * EMB + c];
    __syncthreads();
    float s = 0.f;
    #pragma unroll 8
    for (int f = 0; f < EMB; f++) s += wqs[f] * W_in[f * INCH + c];
    g_Weff[e * INCH + c] = s;
    if (c == 0) {
        float sb = 0.f;
        for (int f = 0; f < EMB; f++) sb += wqs[f] * b_in[f];
        g_beff[e] = sb + bq[e];
    }
}

// ======================= elementwise converts =======================
__global__ void cvt_bf16_kernel(__nv_bfloat16* __restrict__ d, const float* __restrict__ s, int n) {
    for (int i = blockIdx.x * blockDim.x + threadIdx.x; i < n; i += gridDim.x * blockDim.x)
        d[i] = __float2bfloat16(s[i]);
}
__global__ void cvt_split_kernel(__nv_bfloat16* __restrict__ hi, __nv_bfloat16* __restrict__ lo,
                                 const float* __restrict__ s, int n) {
    for (int i = blockIdx.x * blockDim.x + threadIdx.x; i < n; i += gridDim.x * blockDim.x) {
        float v = s[i];
        __nv_bfloat16 h = __float2bfloat16(v);
        hi[i] = h;
        lo[i] = __float2bfloat16(v - __bfloat162float(h));
    }
}

// x[b][c][p] fp32 -> xT[b][p][c] bf16
__global__ void xpose_cvt_kernel(const float* __restrict__ x, __nv_bfloat16* __restrict__ xt) {
    __shared__ float t[32][33];
    int b = blockIdx.z;
    int p0 = blockIdx.x * 32, c0 = blockIdx.y * 32;
    int tx = threadIdx.x, ty = threadIdx.y;
    const float* xb = x + (long long)b * INCH * HWPX;
    #pragma unroll
    for (int k = 0; k < 4; k++)
        t[ty + 8 * k][tx] = xb[(long long)(c0 + ty + 8 * k) * HWPX + p0 + tx];
    __syncthreads();
    __nv_bfloat16* xtb = xt + (long long)b * HWPX * INCH;
    #pragma unroll
    for (int k = 0; k < 4; k++)
        xtb[(long long)(p0 + ty + 8 * k) * INCH + c0 + tx] = __float2bfloat16(t[tx][ty + 8 * k]);
}

// ======================= warp-MMA bf16 GEMM (sm_100-safe HMMA path) =======================
// C[bz][m][n] = alpha * sum_pass sum_k A_p[m,k] * B_p[n,k]  (+bias) (mask->-1e9)
// CTA tile 128x128x64, 8 warps (4x2), warp tile 32x64, mma.m16n8k16 bf16.
struct GP {
    const __nv_bfloat16* A[3];
    const __nv_bfloat16* B[3];
    int P, K, lda, ldb, ldc;
    long long bsA, bsB, bsC;
    void* C;  void* C2;        // C2 = lo buffer for split
    int out_kind;              // 0=f32, 1=bf16, 2=split(hi/lo bf16)
    const float* bias; int bias_per_m;
    float alpha;
    const void* mask; long long bsMask;
};

#define RS 72                      // smem row stride in elements (BK=64 + 8 pad)
#define TILE_B (128 * RS * 2)      // 18432 bytes per tile
#define TG_SMEM (4 * TILE_B)       // A0,B0,A1,B1 = 73728 bytes

// Fill one 128-row x 64-col bf16 tile (row k-contiguous) via cp.async
__device__ __forceinline__ void fill_tile(uint32_t sbase, const __nv_bfloat16* g, int ld, int tid) {
    #pragma unroll
    for (int i = 0; i < 4; i++) {
        int idx = tid + i * 256;
        int r = idx >> 3, c = idx & 7;
        cp_async16(sbase + (r * RS + c * 8) * 2, g + (long long)r * ld + c * 8);
    }
}

__global__ void __launch_bounds__(256)
tgemm_kernel(GP p) {
    extern __shared__ char smem_raw[];
    uint32_t sb = smem_u32(smem_raw);
    const int tid = threadIdx.x, wid = tid >> 5, lane = tid & 31;
    const int bz = blockIdx.z;
    const int m0 = blockIdx.y * 128, n0 = blockIdx.x * 128;
    const int warp_m = wid & 3, warp_n = wid >> 2;  // 4x2 warp grid

    const uint32_t smA[2] = { sb, sb + 2 * TILE_B };
    const uint32_t smB[2] = { sb + TILE_B, sb + 3 * TILE_B };

    const __nv_bfloat16* Ab[3];
    const __nv_bfloat16* Bb[3];
    #pragma unroll
    for (int i = 0; i < 3; i++) {
        Ab[i] = p.A[i] + (long long)bz * p.bsA + (long long)m0 * p.lda;
        Bb[i] = p.B[i] + (long long)bz * p.bsB + (long long)n0 * p.ldb;
    }
    const int cpp = p.K >> 6;
    const int total = p.P * cpp;

    // ldmatrix lane-address offsets (bytes, relative to tile base)
    uint32_t aOff[2];
    #pragma unroll
    for (int i = 0; i < 2; i++)
        aOff[i] = ((warp_m * 32 + i * 16 + (lane & 15)) * RS + ((lane >> 4) << 3)) * 2;
    uint32_t bOff[4];
    #pragma unroll
    for (int j = 0; j < 4; j++)
        bOff[j] = ((warp_n * 64 + j * 16 + (lane & 7) + ((lane >> 4) << 3)) * RS
                   + (((lane >> 3) & 1) << 3)) * 2;

    float acc[2][8][4];
    #pragma unroll
    for (int i = 0; i < 2; i++)
        #pragma unroll
        for (int j = 0; j < 8; j++)
            #pragma unroll
            for (int q = 0; q < 4; q++) acc[i][j][q] = 0.f;

    // prime buffer 0
    fill_tile(smA[0], Ab[0], p.lda, tid);
    fill_tile(smB[0], Bb[0], p.ldb, tid);
    CP_COMMIT();

    for (int c = 0; c < total; c++) {
        int cur = c & 1;
        if (c + 1 < total) {
            int nb = cur ^ 1;
            int cn = c + 1, pp = cn / cpp;
            int k0 = (cn - pp * cpp) << 6;
            fill_tile(smA[nb], Ab[pp] + k0, p.lda, tid);
            fill_tile(smB[nb], Bb[pp] + k0, p.ldb, tid);
            CP_COMMIT();
            CP_WAIT1();
        } else {
            CP_WAIT0();
        }
        __syncthreads();

        #pragma unroll
        for (int ks = 0; ks < 4; ks++) {
            uint32_t a[2][4];
            #pragma unroll
            for (int i = 0; i < 2; i++)
                ldsm4(a[i], smA[cur] + aOff[i] + ks * 32);
            #pragma unroll
            for (int jn = 0; jn < 4; jn++) {
                uint32_t b[4];
                ldsm4(b, smB[cur] + bOff[jn] + ks * 32);
                #pragma unroll
                for (int i = 0; i < 2; i++) {
                    mma16816(acc[i][2 * jn],     a[i], b[0], b[1]);
                    mma16816(acc[i][2 * jn + 1], a[i], b[2], b[3]);
                }
            }
        }
        __syncthreads();
    }

    // ---- epilogue ----
    const int g = lane >> 2, t = lane & 3;
    const int mmode = p.mask ? g_mask_mode : 0;
    const int rbase = m0 + warp_m * 32;
    const int cbase = n0 + warp_n * 64;

    #pragma unroll
    for (int i = 0; i < 2; i++) {
        #pragma unroll
        for (int rr = 0; rr < 2; rr++) {
            int m = rbase + i * 16 + g + rr * 8;
            float bm = (p.bias && p.bias_per_m) ? p.bias[m] : 0.f;
            long long rowoff = (long long)bz * p.bsC + (long long)m * p.ldc;
            long long mrowoff = p.mask ? ((long long)bz * p.bsMask + (long long)m * p.ldc) : 0;
            #pragma unroll
            for (int j = 0; j < 8; j++) {
                int n = cbase + j * 8 + 2 * t;
                float v0 = acc[i][j][rr * 2 + 0] * p.alpha + bm;
                float v1 = acc[i][j][rr * 2 + 1] * p.alpha + bm;
                if (p.bias && !p.bias_per_m) { v0 += p.bias[n]; v1 += p.bias[n + 1]; }
                if (p.mask) {
                    bool mk0, mk1;
                    if (mmode == 0) {
                        mk0 = ((const unsigned char*)p.mask)[mrowoff + n] != 0;
                        mk1 = ((const unsigned char*)p.mask)[mrowoff + n + 1] != 0;
                    } else if (mmode == 1) {
                        mk0 = ((const int*)p.mask)[mrowoff + n] != 0;
                        mk1 = ((const int*)p.mask)[mrowoff + n + 1] != 0;
                    } else {
                        mk0 = ((const float*)p.mask)[mrowoff + n] != 0.f;
                        mk1 = ((const float*)p.mask)[mrowoff + n + 1] != 0.f;
                    }
                    if (mk0) v0 = -1e9f;
                    if (mk1) v1 = -1e9f;
                }
                if (p.out_kind == 0) {
                    *(float2*)((float*)p.C + rowoff + n) = make_float2(v0, v1);
                } else if (p.out_kind == 1) {
                    __nv_bfloat162 pk;
                    pk.x = __float2bfloat16(v0);
                    pk.y = __float2bfloat16(v1);
                    *(__nv_bfloat162*)((__nv_bfloat16*)p.C + rowoff + n) = pk;
                } else {
                    __nv_bfloat162 ph, pl;
                    ph.x = __float2bfloat16(v0);
                    ph.y = __float2bfloat16(v1);
                    pl.x = __float2bfloat16(v0 - __bfloat162float(ph.x));
                    pl.y = __float2bfloat16(v1 - __bfloat162float(ph.y));
                    *(__nv_bfloat162*)((__nv_bfloat16*)p.C + rowoff + n) = ph;
                    *(__nv_bfloat162*)((__nv_bfloat16*)p.C2 + rowoff + n) = pl;
                }
            }
        }
    }
}

// ======================= softmax + hi/lo split =======================
// Each thread owns elements [4t..4t+3] and [1024+4t..1024+4t+3] of the row.
// bf16 hi/lo stored as two 8-byte uint2 chunks at the SAME element positions.
__global__ void __launch_bounds__(256) softmax_split_kernel(float* __restrict__ att,
                                                            __nv_bfloat16* __restrict__ hi,
                                                            __nv_bfloat16* __restrict__ lo) {
    __shared__ float red[8];
    long long row = blockIdx.x;
    float* pr = att + row * SEQ;
    const int t = threadIdx.x;
    float4* p4 = (float4*)pr;
    float4 a = p4[t];
    float4 b = p4[t + 256];
    float x[8] = {a.x, a.y, a.z, a.w, b.x, b.y, b.z, b.w};

    float m = x[0];
    #pragma unroll
    for (int i = 1; i < 8; i++) m = fmaxf(m, x[i]);
    #pragma unroll
    for (int o = 16; o; o >>= 1) m = fmaxf(m, __shfl_xor_sync(0xffffffffu, m, o));
    if ((t & 31) == 0) red[t >> 5] = m;
    __syncthreads();
    float mm = red[0];
    #pragma unroll
    for (int i = 1; i < 8; i++) mm = fmaxf(mm, red[i]);
    __syncthreads();

    float e[8], s = 0.f;
    #pragma unroll
    for (int i = 0; i < 8; i++) { e[i] = __expf(x[i] - mm); s += e[i]; }
    #pragma unroll
    for (int o = 16; o; o >>= 1) s += __shfl_xor_sync(0xffffffffu, s, o);
    if ((t & 31) == 0) red[t >> 5] = s;
    __syncthreads();
    float ss = red[0];
    #pragma unroll
    for (int i = 1; i < 8; i++) ss += red[i];
    float inv = 1.f / ss;

    float r8[8];
    #pragma unroll
    for (int i = 0; i < 8; i++) r8[i] = e[i] * inv;
    p4[t]       = make_float4(r8[0], r8[1], r8[2], r8[3]);
    p4[t + 256] = make_float4(r8[4], r8[5], r8[6], r8[7]);

    __nv_bfloat16* hr = hi + row * SEQ;
    __nv_bfloat16* lr = lo + row * SEQ;
    __align__(8) __nv_bfloat162 h2[4], l2[4];
    #pragma unroll
    for (int i = 0; i < 4; i++) {
        float v0 = r8[2*i], v1 = r8[2*i+1];
        __nv_bfloat16 h0 = __float2bfloat16(v0), h1 = __float2bfloat16(v1);
        h2[i].x = h0; h2[i].y = h1;
        l2[i].x = __float2bfloat16(v0 - __bfloat162float(h0));
        l2[i].y = __float2bfloat16(v1 - __bfloat162float(h1));
    }
    ((uint2*)hr)[t]       = ((uint2*)h2)[0];
    ((uint2*)hr)[256 + t] = ((uint2*)h2)[1];
    ((uint2*)lr)[t]       = ((uint2*)l2)[0];
    ((uint2*)lr)[256 + t] = ((uint2*)l2)[1];
}

// ======================= launch =======================
static void launch_tgemm(const __nv_bfloat16* A0, const __nv_bfloat16* A1, const __nv_bfloat16* A2,
                         const __nv_bfloat16* B0, const __nv_bfloat16* B1, const __nv_bfloat16* B2,
                         int P, int M, int N, int K, int lda, int ldb, int ldc,
                         long long bsA, long long bsB, long long bsC,
                         void* C, void* C2, int out_kind,
                         const float* bias, int bias_per_m, float alpha,
                         const void* mask, long long bsMask) {
    GP p;
    p.A[0] = A0; p.A[1] = A1 ? A1 : A0; p.A[2] = A2 ? A2 : A0;
    p.B[0] = B0; p.B[1] = B1 ? B1 : B0; p.B[2] = B2 ? B2 : B0;
    p.P = P; p.K = K; p.lda = lda; p.ldb = ldb; p.ldc = ldc;
    p.bsA = bsA; p.bsB = bsB; p.bsC = bsC;
    p.C = C; p.C2 = C2; p.out_kind = out_kind;
    p.bias = bias; p.bias_per_m = bias_per_m; p.alpha = alpha;
    p.mask = mask; p.bsMask = bsMask;
    dim3 grid(N / 128, M / 128, BATCH);
    tgemm_kernel<<<grid, 256, TG_SMEM>>>(p);
}

extern "C" void kernel_launch(void* const* d_in, const int* in_sizes, int n_in,
                              void* d_out, int out_size) {
    const float* x     = (const float*)d_in[0];
    const float* ctx   = (const float*)d_in[1];
    const void*  mask  = d_in[2];
    const float* W_in  = (const float*)d_in[3];
    const float* b_in  = (const float*)d_in[4];
    const float* Wq    = (const float*)d_in[5];
    const float* bq    = (const float*)d_in[6];
    const float* Wk    = (const float*)d_in[7];
    const float* bk    = (const float*)d_in[8];
    const float* Wv    = (const float*)d_in[9];
    const float* bv    = (const float*)d_in[10];
    const float* W_out = (const float*)d_in[11];
    const float* b_out = (const float*)d_in[12];

    float* out = (float*)d_out;
    float* att = out + (long long)BATCH * INCH * HWPX;

    // Idempotent host-side attribute set (no static guard — harness rule).
    cudaFuncSetAttribute(tgemm_kernel, cudaFuncAttributeMaxDynamicSharedMemorySize, TG_SMEM);

    float *pWeff, *pbeff;
    __nv_bfloat16 *pxT, *pWeffb, *pWkb, *pWvh, *pWvl, *pWoh, *pWol, *pch, *pcl;
    __nv_bfloat16 *pQ, *pK, *pVh, *pVl, *pAh, *pAl, *pOh, *pOl;
    cudaGetSymbolAddress((void**)&pWeff, g_Weff);
    cudaGetSymbolAddress((void**)&pbeff, g_beff);
    cudaGetSymbolAddress((void**)&pxT, g_xTb);
    cudaGetSymbolAddress((void**)&pWeffb, g_Weffb);
    cudaGetSymbolAddress((void**)&pWkb, g_Wkb);
    cudaGetSymbolAddress((void**)&pWvh, g_Wvh);
    cudaGetSymbolAddress((void**)&pWvl, g_Wvl);
    cudaGetSymbolAddress((void**)&pWoh, g_Wouth);
    cudaGetSymbolAddress((void**)&pWol, g_Woutl);
    cudaGetSymbolAddress((void**)&pch, g_ctxh);
    cudaGetSymbolAddress((void**)&pcl, g_ctxl);
    cudaGetSymbolAddress((void**)&pQ, g_Qb);
    cudaGetSymbolAddress((void**)&pK, g_Kb);
    cudaGetSymbolAddress((void**)&pVh, g_Vth);
    cudaGetSymbolAddress((void**)&pVl, g_Vtl);
    cudaGetSymbolAddress((void**)&pAh, g_atth);
    cudaGetSymbolAddress((void**)&pAl, g_attl);
    cudaGetSymbolAddress((void**)&pOh, g_Oh);
    cudaGetSymbolAddress((void**)&pOl, g_Ol);

    // mask dtype detection
    int scan = 65536;
    if (in_sizes[2] < scan) scan = in_sizes[2];
    detect_mask_kernel<<<1, 256>>>((const unsigned char*)mask, scan);

    // fused in-proj weight + converts
    weff_kernel<<<EMB, 256>>>(Wq, W_in, b_in, bq);
    cvt_bf16_kernel<<<64, 256>>>(pWeffb, pWeff, EMB * INCH);
    cvt_bf16_kernel<<<64, 256>>>(pWkb, Wk, EMB * CTXD);
    cvt_split_kernel<<<64, 256>>>(pWvh, pWvl, Wv, EMB * CTXD);
    cvt_split_kernel<<<64, 256>>>(pWoh, pWol, W_out, INCH * EMB);
    cvt_split_kernel<<<1024, 256>>>(pch, pcl, ctx, BATCH * SEQ * CTXD);
    xpose_cvt_kernel<<<dim3(HWPX / 32, INCH / 32, BATCH), dim3(32, 8)>>>(x, pxT);

    // Q-proj (bf16): Q[p,e] = xT[p,c] . Weff[e,c] + beff[e]
    launch_tgemm(pxT, 0, 0, pWeffb, 0, 0, 1, HWPX, EMB, INCH,
                 INCH, INCH, EMB, (long long)HWPX * INCH, 0, (long long)HWPX * EMB,
                 pQ, 0, 1, pbeff, 0, 1.f, 0, 0);
    // K-proj (bf16): K[s,e] = ctx[s,d] . Wk[e,d] + bk[e]
    launch_tgemm(pch, 0, 0, pWkb, 0, 0, 1, SEQ, EMB, CTXD,
                 CTXD, CTXD, EMB, (long long)SEQ * CTXD, 0, (long long)SEQ * EMB,
                 pK, 0, 1, bk, 0, 1.f, 0, 0);
    // V-proj (split, 3-pass exact): Vt[e,s] = Wv[e,d] . ctx[s,d] + bv[e]
    launch_tgemm(pWvh, pWvl, pWvh, pch, pch, pcl, 3, EMB, SEQ, CTXD,
                 CTXD, CTXD, SEQ, 0, (long long)SEQ * CTXD, (long long)EMB * SEQ,
                 pVh, pVl, 2, bv, 1, 1.f, 0, 0);
    // logits: att[p,s] = (1/16) Q[p,e] . K[s,e], mask -> -1e9 (fp32 into d_out)
    launch_tgemm(pQ, 0, 0, pK, 0, 0, 1, HWPX, SEQ, EMB,
                 EMB, EMB, SEQ, (long long)HWPX * EMB, (long long)SEQ * EMB, (long long)HWPX * SEQ,
                 att, 0, 0, 0, 0, 0.0625f, mask, (long long)HWPX * SEQ);
    // softmax + split
    softmax_split_kernel<<<BATCH * HWPX, 256>>>(att, pAh, pAl);
    // O = att . V (3-pass split) -> O hi/lo
    launch_tgemm(pAh, pAh, pAl, pVh, pVl, pVh, 3, HWPX, EMB, SEQ,
                 SEQ, SEQ, EMB, (long long)HWPX * SEQ, (long long)EMB * SEQ, (long long)HWPX * EMB,
                 pOh, pOl, 2, 0, 0, 1.f, 0, 0);
    // out[c,p] = W_out[c,e] . O[p,e] + b_out[c] (3-pass split, fp32)
    launch_tgemm(pWoh, pWol, pWoh, pOh, pOh, pOl, 3, INCH, HWPX, EMB,
                 EMB, EMB, HWPX, 0, (long long)HWPX * EMB, (long long)INCH * HWPX,
                 out, 0, 0, b_out, 1, 1.f, 0, 0);
}

// round 8
// speedup vs baseline: 4.2443x; 1.4351x over previous
#include <cuda_runtime.h>
#include <cuda_fp16.h>
#include <cstdint>

// Problem constants
#define BATCH 16
#define INCH  256
#define HWPX  2304
#define SEQ   2048
#define CTXD  128
#define EMB   256

// ======================= PTX helpers =======================
__device__ __forceinline__ uint32_t smem_u32(const void* p) {
    uint32_t a;
    asm("{ .reg .u64 t; cvta.to.shared.u64 t, %1; cvt.u32.u64 %0, t; }" : "=r"(a) : "l"(p));
    return a;
}
__device__ __forceinline__ void cp_async16(uint32_t dst, const void* src) {
    asm volatile("cp.async.cg.shared.global [%0], [%1], 16;" :: "r"(dst), "l"(src));
}
#define CP_COMMIT() asm volatile("cp.async.commit_group;" ::: "memory")
#define CP_WAIT0()  asm volatile("cp.async.wait_group 0;" ::: "memory")
#define CP_WAIT1()  asm volatile("cp.async.wait_group 1;" ::: "memory")

__device__ __forceinline__ void ldsm4(uint32_t* r, uint32_t addr) {
    asm volatile("ldmatrix.sync.aligned.m8n8.x4.shared.b16 {%0,%1,%2,%3}, [%4];"
        : "=r"(r[0]), "=r"(r[1]), "=r"(r[2]), "=r"(r[3]) : "r"(addr));
}
__device__ __forceinline__ void mma16816(float* c, const uint32_t* a, uint32_t b0, uint32_t b1) {
    asm volatile("mma.sync.aligned.m16n8k16.row.col.f32.f16.f16.f32 "
        "{%0,%1,%2,%3}, {%4,%5,%6,%7}, {%8,%9}, {%0,%1,%2,%3};"
        : "+f"(c[0]), "+f"(c[1]), "+f"(c[2]), "+f"(c[3])
        : "r"(a[0]), "r"(a[1]), "r"(a[2]), "r"(a[3]), "r"(b0), "r"(b1));
}

// ======================= scratch =======================
__device__ __align__(16) float g_Weff[EMB * INCH];
__device__ __align__(16) float g_beff[EMB];
__device__ __align__(16) __half g_xT[BATCH * HWPX * INCH];        // 18.9 MB
__device__ __align__(16) __half g_Weffh[EMB * INCH];
__device__ __align__(16) __half g_Wkh[EMB * CTXD];
__device__ __align__(16) __half g_Wvh[EMB * CTXD];
__device__ __align__(16) __half g_Wouth[INCH * EMB];
__device__ __align__(16) __half g_ctxh[BATCH * SEQ * CTXD];       // 8.4 MB
__device__ __align__(16) __half g_Q[BATCH * HWPX * EMB];          // 18.9 MB
__device__ __align__(16) __half g_K[BATCH * SEQ * EMB];           // 16.8 MB
__device__ __align__(16) __half g_Vt[BATCH * EMB * SEQ];          // 16.8 MB
__device__ __align__(16) __half g_A16[(size_t)BATCH * HWPX * SEQ];// 151 MB
__device__ __align__(16) __half g_O[BATCH * HWPX * EMB];          // 18.9 MB
__device__ int g_mask_mode;

// ======================= mask dtype detection =======================
__global__ void detect_mask_kernel(const unsigned char* __restrict__ m, int nbytes) {
    __shared__ int c1, c23;
    if (threadIdx.x == 0) { c1 = 0; c23 = 0; }
    __syncthreads();
    int l1 = 0, l23 = 0;
    for (int i = threadIdx.x; i < nbytes; i += blockDim.x) {
        unsigned char v = m[i];
        if (v) { int r = i & 3; if (r == 1) l1++; else if (r >= 2) l23++; }
    }
    if (l1) atomicAdd(&c1, l1);
    if (l23) atomicAdd(&c23, l23);
    __syncthreads();
    if (threadIdx.x == 0) g_mask_mode = (c1 > 0) ? 0 : ((c23 > 0) ? 2 : 1);
}

// ======================= Weff = Wq @ W_in (fp32) =======================
__global__ void weff_kernel(const float* __restrict__ Wq, const float* __restrict__ W_in,
                            const float* __restrict__ b_in, const float* __restrict__ bq) {
    __shared__ float wqs[EMB];
    int e = blockIdx.x, c = threadIdx.x;
    wqs[c] = Wq[e * EMB + c];
    __syncthreads();
    float s = 0.f;
    #pragma unroll 8
    for (int f = 0; f < EMB; f++) s += wqs[f] * W_in[f * INCH + c];
    g_Weff[e * INCH + c] = s;
    if (c == 0) {
        float sb = 0.f;
        for (int f = 0; f < EMB; f++) sb += wqs[f] * b_in[f];
        g_beff[e] = sb + bq[e];
    }
}

// ======================= elementwise convert fp32 -> fp16 =======================
__global__ void cvt_half_kernel(__half* __restrict__ d, const float* __restrict__ s, int n) {
    for (int i = blockIdx.x * blockDim.x + threadIdx.x; i < n; i += gridDim.x * blockDim.x)
        d[i] = __float2half_rn(s[i]);
}

// x[b][c][p] fp32 -> xT[b][p][c] fp16
__global__ void xpose_cvt_kernel(const float* __restrict__ x, __half* __restrict__ xt) {
    __shared__ float t[32][33];
    int b = blockIdx.z;
    int p0 = blockIdx.x * 32, c0 = blockIdx.y * 32;
    int tx = threadIdx.x, ty = threadIdx.y;
    const float* xb = x + (long long)b * INCH * HWPX;
    #pragma unroll
    for (int k = 0; k < 4; k++)
        t[ty + 8 * k][tx] = xb[(long long)(c0 + ty + 8 * k) * HWPX + p0 + tx];
    __syncthreads();
    __half* xtb = xt + (long long)b * HWPX * INCH;
    #pragma unroll
    for (int k = 0; k < 4; k++)
        xtb[(long long)(p0 + ty + 8 * k) * INCH + c0 + tx] = __float2half_rn(t[tx][ty + 8 * k]);
}

// ======================= warp-MMA fp16 GEMM =======================
// C[bz][m][n] = alpha * sum_k A[m,k]*B[n,k]  (+bias) (mask->-1e9)
// CTA tile 128x128x64, 8 warps (4x2), warp tile 32x64, mma.m16n8k16 fp16.
struct GP {
    const __half* A;
    const __half* B;
    int K, lda, ldb, ldc;
    long long bsA, bsB, bsC;
    void* C;
    int out_kind;              // 0=f32, 1=fp16
    const float* bias; int bias_per_m;
    float alpha;
    const void* mask; long long bsMask;
};

#define RS 72                      // smem row stride in elements (BK=64 + 8 pad)
#define TILE_B (128 * RS * 2)      // 18432 bytes per tile
#define TG_SMEM (4 * TILE_B)       // A0,B0,A1,B1 = 73728 bytes

// Fill one 128-row x 64-col fp16 tile (row k-contiguous) via cp.async
__device__ __forceinline__ void fill_tile(uint32_t sbase, const __half* g, int ld, int tid) {
    #pragma unroll
    for (int i = 0; i < 4; i++) {
        int idx = tid + i * 256;
        int r = idx >> 3, c = idx & 7;
        cp_async16(sbase + (r * RS + c * 8) * 2, g + (long long)r * ld + c * 8);
    }
}

__global__ void __launch_bounds__(256)
tgemm_kernel(GP p) {
    extern __shared__ char smem_raw[];
    uint32_t sb = smem_u32(smem_raw);
    const int tid = threadIdx.x, wid = tid >> 5, lane = tid & 31;
    const int bz = blockIdx.z;
    const int m0 = blockIdx.y * 128, n0 = blockIdx.x * 128;
    const int warp_m = wid & 3, warp_n = wid >> 2;  // 4x2 warp grid

    const uint32_t smA[2] = { sb, sb + 2 * TILE_B };
    const uint32_t smB[2] = { sb + TILE_B, sb + 3 * TILE_B };

    const __half* Ab = p.A + (long long)bz * p.bsA + (long long)m0 * p.lda;
    const __half* Bb = p.B + (long long)bz * p.bsB + (long long)n0 * p.ldb;
    const int total = p.K >> 6;

    // ldmatrix lane-address offsets (bytes, relative to tile base)
    uint32_t aOff[2];
    #pragma unroll
    for (int i = 0; i < 2; i++)
        aOff[i] = ((warp_m * 32 + i * 16 + (lane & 15)) * RS + ((lane >> 4) << 3)) * 2;
    uint32_t bOff[4];
    #pragma unroll
    for (int j = 0; j < 4; j++)
        bOff[j] = ((warp_n * 64 + j * 16 + (lane & 7) + ((lane >> 4) << 3)) * RS
                   + (((lane >> 3) & 1) << 3)) * 2;

    float acc[2][8][4];
    #pragma unroll
    for (int i = 0; i < 2; i++)
        #pragma unroll
        for (int j = 0; j < 8; j++)
            #pragma unroll
            for (int q = 0; q < 4; q++) acc[i][j][q] = 0.f;

    // prime buffer 0
    fill_tile(smA[0], Ab, p.lda, tid);
    fill_tile(smB[0], Bb, p.ldb, tid);
    CP_COMMIT();

    for (int c = 0; c < total; c++) {
        int cur = c & 1;
        if (c + 1 < total) {
            int nb = cur ^ 1;
            int k0 = (c + 1) << 6;
            fill_tile(smA[nb], Ab + k0, p.lda, tid);
            fill_tile(smB[nb], Bb + k0, p.ldb, tid);
            CP_COMMIT();
            CP_WAIT1();
        } else {
            CP_WAIT0();
        }
        __syncthreads();

        #pragma unroll
        for (int ks = 0; ks < 4; ks++) {
            uint32_t a[2][4];
            #pragma unroll
            for (int i = 0; i < 2; i++)
                ldsm4(a[i], smA[cur] + aOff[i] + ks * 32);
            #pragma unroll
            for (int jn = 0; jn < 4; jn++) {
                uint32_t b[4];
                ldsm4(b, smB[cur] + bOff[jn] + ks * 32);
                #pragma unroll
                for (int i = 0; i < 2; i++) {
                    mma16816(acc[i][2 * jn],     a[i], b[0], b[1]);
                    mma16816(acc[i][2 * jn + 1], a[i], b[2], b[3]);
                }
            }
        }
        __syncthreads();
    }

    // ---- epilogue ----
    const int g = lane >> 2, t = lane & 3;
    const int mmode = p.mask ? g_mask_mode : 0;
    const int rbase = m0 + warp_m * 32;
    const int cbase = n0 + warp_n * 64;

    #pragma unroll
    for (int i = 0; i < 2; i++) {
        #pragma unroll
        for (int rr = 0; rr < 2; rr++) {
            int m = rbase + i * 16 + g + rr * 8;
            float bm = (p.bias && p.bias_per_m) ? p.bias[m] : 0.f;
            long long rowoff = (long long)bz * p.bsC + (long long)m * p.ldc;
            long long mrowoff = p.mask ? ((long long)bz * p.bsMask + (long long)m * p.ldc) : 0;
            #pragma unroll
            for (int j = 0; j < 8; j++) {
                int n = cbase + j * 8 + 2 * t;
                float v0 = acc[i][j][rr * 2 + 0] * p.alpha + bm;
                float v1 = acc[i][j][rr * 2 + 1] * p.alpha + bm;
                if (p.bias && !p.bias_per_m) { v0 += p.bias[n]; v1 += p.bias[n + 1]; }
                if (p.mask) {
                    bool mk0, mk1;
                    if (mmode == 0) {
                        mk0 = ((const unsigned char*)p.mask)[mrowoff + n] != 0;
                        mk1 = ((const unsigned char*)p.mask)[mrowoff + n + 1] != 0;
                    } else if (mmode == 1) {
                        mk0 = ((const int*)p.mask)[mrowoff + n] != 0;
                        mk1 = ((const int*)p.mask)[mrowoff + n + 1] != 0;
                    } else {
                        mk0 = ((const float*)p.mask)[mrowoff + n] != 0.f;
                        mk1 = ((const float*)p.mask)[mrowoff + n + 1] != 0.f;
                    }
                    if (mk0) v0 = -1e9f;
                    if (mk1) v1 = -1e9f;
                }
                if (p.out_kind == 0) {
                    *(float2*)((float*)p.C + rowoff + n) = make_float2(v0, v1);
                } else {
                    __half2 pk;
                    pk.x = __float2half_rn(v0);
                    pk.y = __float2half_rn(v1);
                    *(__half2*)((__half*)p.C + rowoff + n) = pk;
                }
            }
        }
    }
}

// ======================= softmax (fp32 in place) + fp16 copy =======================
// Each thread owns elements [4t..4t+3] and [1024+4t..1024+4t+3] of the row.
__global__ void __launch_bounds__(256) softmax_kernel(float* __restrict__ att,
                                                      __half* __restrict__ a16) {
    __shared__ float red[8];
    long long row = blockIdx.x;
    float* pr = att + row * SEQ;
    const int t = threadIdx.x;
    float4* p4 = (float4*)pr;
    float4 a = p4[t];
    float4 b = p4[t + 256];
    float x[8] = {a.x, a.y, a.z, a.w, b.x, b.y, b.z, b.w};

    float m = x[0];
    #pragma unroll
    for (int i = 1; i < 8; i++) m = fmaxf(m, x[i]);
    #pragma unroll
    for (int o = 16; o; o >>= 1) m = fmaxf(m, __shfl_xor_sync(0xffffffffu, m, o));
    if ((t & 31) == 0) red[t >> 5] = m;
    __syncthreads();
    float mm = red[0];
    #pragma unroll
    for (int i = 1; i < 8; i++) mm = fmaxf(mm, red[i]);
    __syncthreads();

    float e[8], s = 0.f;
    #pragma unroll
    for (int i = 0; i < 8; i++) { e[i] = __expf(x[i] - mm); s += e[i]; }
    #pragma unroll
    for (int o = 16; o; o >>= 1) s += __shfl_xor_sync(0xffffffffu, s, o);
    if ((t & 31) == 0) red[t >> 5] = s;
    __syncthreads();
    float ss = red[0];
    #pragma unroll
    for (int i = 1; i < 8; i++) ss += red[i];
    float inv = 1.f / ss;

    float r8[8];
    #pragma unroll
    for (int i = 0; i < 8; i++) r8[i] = e[i] * inv;
    p4[t]       = make_float4(r8[0], r8[1], r8[2], r8[3]);
    p4[t + 256] = make_float4(r8[4], r8[5], r8[6], r8[7]);

    __half* hr = a16 + row * SEQ;
    __align__(8) __half2 h2[4];
    #pragma unroll
    for (int i = 0; i < 4; i++) {
        h2[i].x = __float2half_rn(r8[2*i]);
        h2[i].y = __float2half_rn(r8[2*i+1]);
    }
    ((uint2*)hr)[t]       = ((uint2*)h2)[0];
    ((uint2*)hr)[256 + t] = ((uint2*)h2)[1];
}

// ======================= launch =======================
static void launch_tgemm(const __half* A, const __half* B,
                         int M, int N, int K, int lda, int ldb, int ldc,
                         long long bsA, long long bsB, long long bsC,
                         void* C, int out_kind,
                         const float* bias, int bias_per_m, float alpha,
                         const void* mask, long long bsMask) {
    GP p;
    p.A = A; p.B = B;
    p.K = K; p.lda = lda; p.ldb = ldb; p.ldc = ldc;
    p.bsA = bsA; p.bsB = bsB; p.bsC = bsC;
    p.C = C; p.out_kind = out_kind;
    p.bias = bias; p.bias_per_m = bias_per_m; p.alpha = alpha;
    p.mask = mask; p.bsMask = bsMask;
    dim3 grid(N / 128, M / 128, BATCH);
    tgemm_kernel<<<grid, 256, TG_SMEM>>>(p);
}

extern "C" void kernel_launch(void* const* d_in, const int* in_sizes, int n_in,
                              void* d_out, int out_size) {
    const float* x     = (const float*)d_in[0];
    const float* ctx   = (const float*)d_in[1];
    const void*  mask  = d_in[2];
    const float* W_in  = (const float*)d_in[3];
    const float* b_in  = (const float*)d_in[4];
    const float* Wq    = (const float*)d_in[5];
    const float* bq    = (const float*)d_in[6];
    const float* Wk    = (const float*)d_in[7];
    const float* bk    = (const float*)d_in[8];
    const float* Wv    = (const float*)d_in[9];
    const float* bv    = (const float*)d_in[10];
    const float* W_out = (const float*)d_in[11];
    const float* b_out = (const float*)d_in[12];

    float* out = (float*)d_out;
    float* att = out + (long long)BATCH * INCH * HWPX;

    cudaFuncSetAttribute(tgemm_kernel, cudaFuncAttributeMaxDynamicSharedMemorySize, TG_SMEM);

    float *pWeff, *pbeff;
    __half *pxT, *pWeffh, *pWkh, *pWvh, *pWoh, *pctx, *pQ, *pK, *pVt, *pA16, *pO;
    cudaGetSymbolAddress((void**)&pWeff, g_Weff);
    cudaGetSymbolAddress((void**)&pbeff, g_beff);
    cudaGetSymbolAddress((void**)&pxT, g_xT);
    cudaGetSymbolAddress((void**)&pWeffh, g_Weffh);
    cudaGetSymbolAddress((void**)&pWkh, g_Wkh);
    cudaGetSymbolAddress((void**)&pWvh, g_Wvh);
    cudaGetSymbolAddress((void**)&pWoh, g_Wouth);
    cudaGetSymbolAddress((void**)&pctx, g_ctxh);
    cudaGetSymbolAddress((void**)&pQ, g_Q);
    cudaGetSymbolAddress((void**)&pK, g_K);
    cudaGetSymbolAddress((void**)&pVt, g_Vt);
    cudaGetSymbolAddress((void**)&pA16, g_A16);
    cudaGetSymbolAddress((void**)&pO, g_O);

    // mask dtype detection
    int scan = 65536;
    if (in_sizes[2] < scan) scan = in_sizes[2];
    detect_mask_kernel<<<1, 256>>>((const unsigned char*)mask, scan);

    // fused in-proj weight + converts (all fp16)
    weff_kernel<<<EMB, 256>>>(Wq, W_in, b_in, bq);
    cvt_half_kernel<<<64, 256>>>(pWeffh, pWeff, EMB * INCH);
    cvt_half_kernel<<<64, 256>>>(pWkh, Wk, EMB * CTXD);
    cvt_half_kernel<<<64, 256>>>(pWvh, Wv, EMB * CTXD);
    cvt_half_kernel<<<64, 256>>>(pWoh, W_out, INCH * EMB);
    cvt_half_kernel<<<1024, 256>>>(pctx, ctx, BATCH * SEQ * CTXD);
    xpose_cvt_kernel<<<dim3(HWPX / 32, INCH / 32, BATCH), dim3(32, 8)>>>(x, pxT);

    // Q-proj: Q[p,e] = xT[p,c] . Weff[e,c] + beff[e]   (fp16 out)
    launch_tgemm(pxT, pWeffh, HWPX, EMB, INCH,
                 INCH, INCH, EMB, (long long)HWPX * INCH, 0, (long long)HWPX * EMB,
                 pQ, 1, pbeff, 0, 1.f, 0, 0);
    // K-proj: K[s,e] = ctx[s,d] . Wk[e,d] + bk[e]      (fp16 out)
    launch_tgemm(pctx, pWkh, SEQ, EMB, CTXD,
                 CTXD, CTXD, EMB, (long long)SEQ * CTXD, 0, (long long)SEQ * EMB,
                 pK, 1, bk, 0, 1.f, 0, 0);
    // V-proj: Vt[e,s] = Wv[e,d] . ctx[s,d] + bv[e]     (fp16 out)
    launch_tgemm(pWvh, pctx, EMB, SEQ, CTXD,
                 CTXD, CTXD, SEQ, 0, (long long)SEQ * CTXD, (long long)EMB * SEQ,
                 pVt, 1, bv, 1, 1.f, 0, 0);
    // logits: att[p,s] = (1/16) Q[p,e] . K[s,e], mask -> -1e9 (fp32 into d_out)
    launch_tgemm(pQ, pK, HWPX, SEQ, EMB,
                 EMB, EMB, SEQ, (long long)HWPX * EMB, (long long)SEQ * EMB, (long long)HWPX * SEQ,
                 att, 0, 0, 0, 0.0625f, mask, (long long)HWPX * SEQ);
    // softmax (fp32 in place) + fp16 copy
    softmax_kernel<<<BATCH * HWPX, 256>>>(att, pA16);
    // O[p,e] = att[p,s] . Vt[e,s]                      (fp16 out)
    launch_tgemm(pA16, pVt, HWPX, EMB, SEQ,
                 SEQ, SEQ, EMB, (long long)HWPX * SEQ, (long long)EMB * SEQ, (long long)HWPX * EMB,
                 pO, 1, 0, 0, 1.f, 0, 0);
    // out[c,p] = W_out[c,e] . O[p,e] + b_out[c]        (fp32 out)
    launch_tgemm(pWoh, pO, INCH, HWPX, EMB,
                 EMB, EMB, HWPX, 0, (long long)HWPX * EMB, (long long)INCH * HWPX,
                 out, 0, b_out, 1, 1.f, 0, 0);
}

// round 9
// speedup vs baseline: 4.4136x; 1.0399x over previous
#include <cuda_runtime.h>
#include <cuda_fp16.h>
#include <cstdint>

// Problem constants
#define BATCH 16
#define INCH  256
#define HWPX  2304
#define SEQ   2048
#define CTXD  128
#define EMB   256

// ======================= PTX helpers =======================
__device__ __forceinline__ uint32_t smem_u32(const void* p) {
    uint32_t a;
    asm("{ .reg .u64 t; cvta.to.shared.u64 t, %1; cvt.u32.u64 %0, t; }" : "=r"(a) : "l"(p));
    return a;
}
__device__ __forceinline__ void cp_async16(uint32_t dst, const void* src) {
    asm volatile("cp.async.cg.shared.global [%0], [%1], 16;" :: "r"(dst), "l"(src));
}
#define CP_COMMIT() asm volatile("cp.async.commit_group;" ::: "memory")
#define CP_WAIT0()  asm volatile("cp.async.wait_group 0;" ::: "memory")
#define CP_WAIT1()  asm volatile("cp.async.wait_group 1;" ::: "memory")

__device__ __forceinline__ void ldsm4(uint32_t* r, uint32_t addr) {
    asm volatile("ldmatrix.sync.aligned.m8n8.x4.shared.b16 {%0,%1,%2,%3}, [%4];"
        : "=r"(r[0]), "=r"(r[1]), "=r"(r[2]), "=r"(r[3]) : "r"(addr));
}
__device__ __forceinline__ void ldsm4t(uint32_t* r, uint32_t addr) {
    asm volatile("ldmatrix.sync.aligned.m8n8.x4.trans.shared.b16 {%0,%1,%2,%3}, [%4];"
        : "=r"(r[0]), "=r"(r[1]), "=r"(r[2]), "=r"(r[3]) : "r"(addr));
}
__device__ __forceinline__ void mma16816(float* c, const uint32_t* a, uint32_t b0, uint32_t b1) {
    asm volatile("mma.sync.aligned.m16n8k16.row.col.f32.f16.f16.f32 "
        "{%0,%1,%2,%3}, {%4,%5,%6,%7}, {%8,%9}, {%0,%1,%2,%3};"
        : "+f"(c[0]), "+f"(c[1]), "+f"(c[2]), "+f"(c[3])
        : "r"(a[0]), "r"(a[1]), "r"(a[2]), "r"(a[3]), "r"(b0), "r"(b1));
}

// ======================= scratch =======================
__device__ __align__(16) float g_Weff[EMB * INCH];
__device__ __align__(16) float g_beff[EMB];
__device__ __align__(16) __half g_Weffh[EMB * INCH];
__device__ __align__(16) __half g_Wkh[EMB * CTXD];
__device__ __align__(16) __half g_Wvh[EMB * CTXD];
__device__ __align__(16) __half g_Wouth[INCH * EMB];
__device__ __align__(16) __half g_Q[BATCH * HWPX * EMB];           // 18.9 MB
__device__ __align__(16) __half g_K[BATCH * SEQ * EMB];            // 16.8 MB
__device__ __align__(16) __half g_Vt[BATCH * EMB * SEQ];           // 16.8 MB
__device__ __align__(16) __half g_A16[(size_t)BATCH * HWPX * SEQ]; // 151 MB (logits, then normalized)
__device__ __align__(16) __half g_O[BATCH * HWPX * EMB];           // 18.9 MB
__device__ int g_mask_mode;

// ======================= mask dtype detection =======================
__global__ void detect_mask_kernel(const unsigned char* __restrict__ m, int nbytes) {
    __shared__ int c1, c23;
    if (threadIdx.x == 0) { c1 = 0; c23 = 0; }
    __syncthreads();
    int l1 = 0, l23 = 0;
    for (int i = threadIdx.x; i < nbytes; i += blockDim.x) {
        unsigned char v = m[i];
        if (v) { int r = i & 3; if (r == 1) l1++; else if (r >= 2) l23++; }
    }
    if (l1) atomicAdd(&c1, l1);
    if (l23) atomicAdd(&c23, l23);
    __syncthreads();
    if (threadIdx.x == 0) g_mask_mode = (c1 > 0) ? 0 : ((c23 > 0) ? 2 : 1);
}

// ======================= Weff = Wq @ W_in (fp32) =======================
__global__ void weff_kernel(const float* __restrict__ Wq, const float* __restrict__ W_in,
                            const float* __restrict__ b_in, const float* __restrict__ bq) {
    __shared__ float wqs[EMB];
    int e = blockIdx.x, c = threadIdx.x;
    wqs[c] = Wq[e * EMB + c];
    __syncthreads();
    float s = 0.f;
    #pragma unroll 8
    for (int f = 0; f < EMB; f++) s += wqs[f] * W_in[f * INCH + c];
    g_Weff[e * INCH + c] = s;
    if (c == 0) {
        float sb = 0.f;
        for (int f = 0; f < EMB; f++) sb += wqs[f] * b_in[f];
        g_beff[e] = sb + bq[e];
    }
}

__global__ void cvt_half_kernel(__half* __restrict__ d, const float* __restrict__ s, int n) {
    for (int i = blockIdx.x * blockDim.x + threadIdx.x; i < n; i += gridDim.x * blockDim.x)
        d[i] = __float2half_rn(s[i]);
}

// ======================= warp-MMA fp16 GEMM =======================
// C[bz][m][n] = alpha * sum_k A[m,k]*B[n,k]  (+bias) (mask->-1e9)
// CTA tile 128x128x64, 8 warps (4x2), warp tile 32x64, mma.m16n8k16 fp16.
// AK: 0 = fp16 [m][k] via cp.async; 1 = fp32 k-contig (convert in reg);
//     2 = fp32 m-contig "transposed" source (x layout) -> smem [k][m], ldmatrix.trans
// BK: 0 = fp16 via cp.async; 1 = fp32 k-contig
struct GP {
    const void* A;
    const void* B;
    int K, lda, ldb, ldc;
    long long bsA, bsB, bsC;
    void* C;
    int out_kind;              // 0=f32, 1=fp16
    const float* bias; int bias_per_m;
    float alpha;
    const void* mask; long long bsMask;
};

#define RS  72                     // fp16 [m][k] row stride (64 + 8 pad)
#define RS2 136                    // [k][m] row stride (128 + 8 pad)
#define TILE_B (128 * RS * 2)      // 18432 bytes (>= 64*RS2*2 = 17408)
#define TG_SMEM (4 * TILE_B)

// fp16 128x64 tile via cp.async
__device__ __forceinline__ void fill16(uint32_t sbase, const __half* g, int ld, int tid) {
    #pragma unroll
    for (int i = 0; i < 4; i++) {
        int idx = tid + i * 256;
        int r = idx >> 3, c = idx & 7;
        cp_async16(sbase + (r * RS + c * 8) * 2, g + (long long)r * ld + c * 8);
    }
}
// fp32 k-contig 128x64 tile -> fp16 smem [m][k] (sync)
__device__ __forceinline__ void fill32k(char* sm, const float* g, int ld, int tid) {
    #pragma unroll
    for (int i = 0; i < 4; i++) {
        int c = tid + i * 256;
        int r = c >> 3, s = c & 7;
        const float4* src = (const float4*)(g + (long long)r * ld + s * 8);
        float4 u = src[0], v = src[1];
        __align__(16) __half2 h[4] = {
            __floats2half2_rn(u.x, u.y), __floats2half2_rn(u.z, u.w),
            __floats2half2_rn(v.x, v.y), __floats2half2_rn(v.z, v.w) };
        *(uint4*)(sm + (r * RS + s * 8) * 2) = *(uint4*)h;
    }
}
// fp32 m-contig source (64 k-rows x 128 m-cols) -> fp16 smem [k][m] (sync)
__device__ __forceinline__ void fill32t(char* sm, const float* g, int ldk, int tid) {
    #pragma unroll
    for (int i = 0; i < 4; i++) {
        int c = tid + i * 256;
        int r = c >> 4, s = c & 15;      // r = k-row (0..63), s = m-seg (0..15)
        const float4* src = (const float4*)(g + (long long)r * ldk + s * 8);
        float4 u = src[0], v = src[1];
        __align__(16) __half2 h[4] = {
            __floats2half2_rn(u.x, u.y), __floats2half2_rn(u.z, u.w),
            __floats2half2_rn(v.x, v.y), __floats2half2_rn(v.z, v.w) };
        *(uint4*)(sm + (r * RS2 + s * 8) * 2) = *(uint4*)h;
    }
}

template<int AK, int BK>
__global__ void __launch_bounds__(256)
tgemm_kernel(GP p) {
    extern __shared__ char smem_raw[];
    char* smc = smem_raw;
    uint32_t sb = smem_u32(smem_raw);
    const int tid = threadIdx.x, wid = tid >> 5, lane = tid & 31;
    const int bz = blockIdx.z;
    const int m0 = blockIdx.y * 128, n0 = blockIdx.x * 128;
    const int warp_m = wid & 3, warp_n = wid >> 2;

    const int offA[2] = { 0, 2 * TILE_B };
    const int offB[2] = { TILE_B, 3 * TILE_B };

    // source base pointers
    const __half* Ah = nullptr; const float* Af = nullptr;
    if (AK == 0) Ah = (const __half*)p.A + (long long)bz * p.bsA + (long long)m0 * p.lda;
    else if (AK == 1) Af = (const float*)p.A + (long long)bz * p.bsA + (long long)m0 * p.lda;
    else Af = (const float*)p.A + (long long)bz * p.bsA + m0;   // + k0*lda per chunk
    const __half* Bh = nullptr; const float* Bf = nullptr;
    if (BK == 0) Bh = (const __half*)p.B + (long long)bz * p.bsB + (long long)n0 * p.ldb;
    else Bf = (const float*)p.B + (long long)bz * p.bsB + (long long)n0 * p.ldb;

    const int total = p.K >> 6;

    // fragment smem offsets
    uint32_t aOff[2], bOff[4];
    if (AK == 2) {
        int t4 = lane >> 3, r = lane & 7;
        #pragma unroll
        for (int i = 0; i < 2; i++)
            aOff[i] = (((t4 >> 1) * 8 + r) * RS2 + warp_m * 32 + i * 16 + (t4 & 1) * 8) * 2;
    } else {
        #pragma unroll
        for (int i = 0; i < 2; i++)
            aOff[i] = ((warp_m * 32 + i * 16 + (lane & 15)) * RS + ((lane >> 4) << 3)) * 2;
    }
    #pragma unroll
    for (int j = 0; j < 4; j++)
        bOff[j] = ((warp_n * 64 + j * 16 + (lane & 7) + ((lane >> 4) << 3)) * RS
                   + (((lane >> 3) & 1) << 3)) * 2;

    float acc[2][8][4];
    #pragma unroll
    for (int i = 0; i < 2; i++)
        #pragma unroll
        for (int j = 0; j < 8; j++)
            #pragma unroll
            for (int q = 0; q < 4; q++) acc[i][j][q] = 0.f;

    auto fillA = [&](int buf, int k0) {
        if (AK == 0)      fill16(sb + offA[buf], Ah + k0, p.lda, tid);
        else if (AK == 1) fill32k(smc + offA[buf], Af + k0, p.lda, tid);
        else              fill32t(smc + offA[buf], Af + (long long)k0 * p.lda, p.lda, tid);
    };
    auto fillB = [&](int buf, int k0) {
        if (BK == 0) fill16(sb + offB[buf], Bh + k0, p.ldb, tid);
        else         fill32k(smc + offB[buf], Bf + k0, p.ldb, tid);
    };

    fillA(0, 0);
    fillB(0, 0);
    CP_COMMIT();

    for (int c = 0; c < total; c++) {
        int cur = c & 1;
        if (c + 1 < total) {
            int nb = cur ^ 1, k0 = (c + 1) << 6;
            fillA(nb, k0);
            fillB(nb, k0);
            CP_COMMIT();
            CP_WAIT1();
        } else {
            CP_WAIT0();
        }
        __syncthreads();

        #pragma unroll
        for (int ks = 0; ks < 4; ks++) {
            uint32_t a[2][4];
            #pragma unroll
            for (int i = 0; i < 2; i++) {
                if (AK == 2) ldsm4t(a[i], sb + offA[cur] + aOff[i] + ks * (16 * RS2 * 2));
                else         ldsm4(a[i], sb + offA[cur] + aOff[i] + ks * 32);
            }
            #pragma unroll
            for (int jn = 0; jn < 4; jn++) {
                uint32_t b[4];
                ldsm4(b, sb + offB[cur] + bOff[jn] + ks * 32);
                #pragma unroll
                for (int i = 0; i < 2; i++) {
                    mma16816(acc[i][2 * jn],     a[i], b[0], b[1]);
                    mma16816(acc[i][2 * jn + 1], a[i], b[2], b[3]);
                }
            }
        }
        __syncthreads();
    }

    // ---- epilogue ----
    const int g = lane >> 2, t = lane & 3;
    const int mmode = p.mask ? g_mask_mode : 0;
    const int rbase = m0 + warp_m * 32;
    const int cbase = n0 + warp_n * 64;

    #pragma unroll
    for (int i = 0; i < 2; i++) {
        #pragma unroll
        for (int rr = 0; rr < 2; rr++) {
            int m = rbase + i * 16 + g + rr * 8;
            float bm = (p.bias && p.bias_per_m) ? p.bias[m] : 0.f;
            long long rowoff = (long long)bz * p.bsC + (long long)m * p.ldc;
            long long mrowoff = p.mask ? ((long long)bz * p.bsMask + (long long)m * p.ldc) : 0;
            #pragma unroll
            for (int j = 0; j < 8; j++) {
                int n = cbase + j * 8 + 2 * t;
                float v0 = acc[i][j][rr * 2 + 0] * p.alpha + bm;
                float v1 = acc[i][j][rr * 2 + 1] * p.alpha + bm;
                if (p.bias && !p.bias_per_m) { v0 += p.bias[n]; v1 += p.bias[n + 1]; }
                if (p.mask) {
                    bool mk0, mk1;
                    if (mmode == 0) {
                        mk0 = ((const unsigned char*)p.mask)[mrowoff + n] != 0;
                        mk1 = ((const unsigned char*)p.mask)[mrowoff + n + 1] != 0;
                    } else if (mmode == 1) {
                        mk0 = ((const int*)p.mask)[mrowoff + n] != 0;
                        mk1 = ((const int*)p.mask)[mrowoff + n + 1] != 0;
                    } else {
                        mk0 = ((const float*)p.mask)[mrowoff + n] != 0.f;
                        mk1 = ((const float*)p.mask)[mrowoff + n + 1] != 0.f;
                    }
                    if (mk0) v0 = -1e9f;
                    if (mk1) v1 = -1e9f;
                }
                if (p.out_kind == 0) {
                    *(float2*)((float*)p.C + rowoff + n) = make_float2(v0, v1);
                } else {
                    __half2 pk;
                    pk.x = __float2half_rn(v0);   // -1e9 -> -inf: exp() = 0, exact
                    pk.y = __float2half_rn(v1);
                    *(__half2*)((__half*)p.C + rowoff + n) = pk;
                }
            }
        }
    }
}

// ======================= softmax: fp16 logits -> fp32 att + fp16 normalized =======================
// Each thread owns 8 contiguous elements [8t .. 8t+7] of the row.
__global__ void __launch_bounds__(256) softmax_kernel(const __half* __restrict__ logits_in,
                                                      float* __restrict__ att,
                                                      __half* __restrict__ a16) {
    __shared__ float red[8];
    long long row = blockIdx.x;
    const int t = threadIdx.x;
    const __half* lr = logits_in + row * SEQ;
    uint4 raw = ((const uint4*)lr)[t];
    __half2* hp = (__half2*)&raw;
    float x[8];
    #pragma unroll
    for (int i = 0; i < 4; i++) {
        float2 f = __half22float2(hp[i]);
        x[2 * i] = f.x; x[2 * i + 1] = f.y;
    }

    float m = x[0];
    #pragma unroll
    for (int i = 1; i < 8; i++) m = fmaxf(m, x[i]);
    #pragma unroll
    for (int o = 16; o; o >>= 1) m = fmaxf(m, __shfl_xor_sync(0xffffffffu, m, o));
    if ((t & 31) == 0) red[t >> 5] = m;
    __syncthreads();
    float mm = red[0];
    #pragma unroll
    for (int i = 1; i < 8; i++) mm = fmaxf(mm, red[i]);
    __syncthreads();

    float e[8], s = 0.f;
    #pragma unroll
    for (int i = 0; i < 8; i++) { e[i] = __expf(x[i] - mm); s += e[i]; }
    #pragma unroll
    for (int o = 16; o; o >>= 1) s += __shfl_xor_sync(0xffffffffu, s, o);
    if ((t & 31) == 0) red[t >> 5] = s;
    __syncthreads();
    float ss = red[0];
    #pragma unroll
    for (int i = 1; i < 8; i++) ss += red[i];
    float inv = 1.f / ss;

    float r8[8];
    #pragma unroll
    for (int i = 0; i < 8; i++) r8[i] = e[i] * inv;

    float* pr = att + row * SEQ;
    *(float4*)(pr + 8 * t)     = make_float4(r8[0], r8[1], r8[2], r8[3]);
    *(float4*)(pr + 8 * t + 4) = make_float4(r8[4], r8[5], r8[6], r8[7]);

    __align__(16) __half2 h2[4];
    #pragma unroll
    for (int i = 0; i < 4; i++) {
        h2[i].x = __float2half_rn(r8[2 * i]);
        h2[i].y = __float2half_rn(r8[2 * i + 1]);
    }
    ((uint4*)(a16 + row * SEQ))[t] = *(uint4*)h2;
}

// ======================= launch =======================
template<int AK, int BK>
static void launch_gemm(const void* A, const void* B,
                        int M, int N, int K, int lda, int ldb, int ldc,
                        long long bsA, long long bsB, long long bsC,
                        void* C, int out_kind,
                        const float* bias, int bias_per_m, float alpha,
                        const void* mask, long long bsMask) {
    GP p;
    p.A = A; p.B = B;
    p.K = K; p.lda = lda; p.ldb = ldb; p.ldc = ldc;
    p.bsA = bsA; p.bsB = bsB; p.bsC = bsC;
    p.C = C; p.out_kind = out_kind;
    p.bias = bias; p.bias_per_m = bias_per_m; p.alpha = alpha;
    p.mask = mask; p.bsMask = bsMask;
    cudaFuncSetAttribute(tgemm_kernel<AK, BK>, cudaFuncAttributeMaxDynamicSharedMemorySize, TG_SMEM);
    dim3 grid(N / 128, M / 128, BATCH);
    tgemm_kernel<AK, BK><<<grid, 256, TG_SMEM>>>(p);
}

extern "C" void kernel_launch(void* const* d_in, const int* in_sizes, int n_in,
                              void* d_out, int out_size) {
    const float* x     = (const float*)d_in[0];
    const float* ctx   = (const float*)d_in[1];
    const void*  mask  = d_in[2];
    const float* W_in  = (const float*)d_in[3];
    const float* b_in  = (const float*)d_in[4];
    const float* Wq    = (const float*)d_in[5];
    const float* bq    = (const float*)d_in[6];
    const float* Wk    = (const float*)d_in[7];
    const float* bk    = (const float*)d_in[8];
    const float* Wv    = (const float*)d_in[9];
    const float* bv    = (const float*)d_in[10];
    const float* W_out = (const float*)d_in[11];
    const float* b_out = (const float*)d_in[12];

    float* out = (float*)d_out;
    float* att = out + (long long)BATCH * INCH * HWPX;

    float *pWeff, *pbeff;
    __half *pWeffh, *pWkh, *pWvh, *pWoh, *pQ, *pK, *pVt, *pA16, *pO;
    cudaGetSymbolAddress((void**)&pWeff, g_Weff);
    cudaGetSymbolAddress((void**)&pbeff, g_beff);
    cudaGetSymbolAddress((void**)&pWeffh, g_Weffh);
    cudaGetSymbolAddress((void**)&pWkh, g_Wkh);
    cudaGetSymbolAddress((void**)&pWvh, g_Wvh);
    cudaGetSymbolAddress((void**)&pWoh, g_Wouth);
    cudaGetSymbolAddress((void**)&pQ, g_Q);
    cudaGetSymbolAddress((void**)&pK, g_K);
    cudaGetSymbolAddress((void**)&pVt, g_Vt);
    cudaGetSymbolAddress((void**)&pA16, g_A16);
    cudaGetSymbolAddress((void**)&pO, g_O);

    // 1: mask dtype detection
    int scan = 65536;
    if (in_sizes[2] < scan) scan = in_sizes[2];
    detect_mask_kernel<<<1, 256>>>((const unsigned char*)mask, scan);
    // 2: Weff = Wq @ W_in
    weff_kernel<<<EMB, 256>>>(Wq, W_in, b_in, bq);
    // 3-5: weight converts
    cvt_half_kernel<<<64, 256>>>(pWeffh, pWeff, EMB * INCH);
    cvt_half_kernel<<<64, 256>>>(pWkh, Wk, EMB * CTXD);
    cvt_half_kernel<<<64, 256>>>(pWvh, Wv, EMB * CTXD);
    // 6: Q-proj (profiled launch): Q[p,e] = x^T[p,c].Weff[e,c] + beff  (A = x fp32 trans path)
    launch_gemm<2, 0>(x, pWeffh, HWPX, EMB, INCH,
                      HWPX, INCH, EMB, (long long)INCH * HWPX, 0, (long long)HWPX * EMB,
                      pQ, 1, pbeff, 0, 1.f, 0, 0);
    // 7: W_out convert
    cvt_half_kernel<<<64, 256>>>(pWoh, W_out, INCH * EMB);
    // 8: K-proj: K[s,e] = ctx[s,d].Wk[e,d] + bk   (A = ctx fp32 direct)
    launch_gemm<1, 0>(ctx, pWkh, SEQ, EMB, CTXD,
                      CTXD, CTXD, EMB, (long long)SEQ * CTXD, 0, (long long)SEQ * EMB,
                      pK, 1, bk, 0, 1.f, 0, 0);
    // 9: V-proj: Vt[e,s] = Wv[e,d].ctx[s,d] + bv  (B = ctx fp32 direct)
    launch_gemm<0, 1>(pWvh, ctx, EMB, SEQ, CTXD,
                      CTXD, CTXD, SEQ, 0, (long long)SEQ * CTXD, (long long)EMB * SEQ,
                      pVt, 1, bv, 1, 1.f, 0, 0);
    // 10: logits (fp16, mask -> -inf) into g_A16
    launch_gemm<0, 0>(pQ, pK, HWPX, SEQ, EMB,
                      EMB, EMB, SEQ, (long long)HWPX * EMB, (long long)SEQ * EMB, (long long)HWPX * SEQ,
                      pA16, 1, 0, 0, 0.0625f, mask, (long long)HWPX * SEQ);
    // 11: softmax: fp16 logits -> fp32 att (d_out) + fp16 normalized (in place)
    softmax_kernel<<<BATCH * HWPX, 256>>>(pA16, att, pA16);
    // 12: O[p,e] = att[p,s].Vt[e,s]
    launch_gemm<0, 0>(pA16, pVt, HWPX, EMB, SEQ,
                      SEQ, SEQ, EMB, (long long)HWPX * SEQ, (long long)EMB * SEQ, (long long)HWPX * EMB,
                      pO, 1, 0, 0, 1.f, 0, 0);
    // 13: out[c,p] = W_out[c,e].O[p,e] + b_out[c]  (fp32)
    launch_gemm<0, 0>(pWoh, pO, INCH, HWPX, EMB,
                      EMB, EMB, HWPX, 0, (long long)HWPX * EMB, (long long)INCH * HWPX,
                      out, 0, b_out, 1, 1.f, 0, 0);
}